// round 15
// baseline (speedup 1.0000x reference)
#include <cuda_runtime.h>

// PoseCost: SE(3) log-map pose error, N = B*H poses.
// Outputs: [0,N) cost | [N,2N) rot_err | [2N,3N) pos_err | [3N,6N) v | [6N,9N) omega
//
// FINAL (converged). 4 poses/thread, independent CTAs, all global traffic
// aligned float4, TPB=256. Reproduced 7x: 59.42-59.52us bench, 55.5-56.8us
// kernel, DRAM 68-69.8%, rel_err 9.4e-6.
//
// Session conclusion (14 rounds, 10 distinct configs): bound by ~5.5 TB/s
// sustained HBM throughput on the fixed 57/43 read/write streaming mix;
// 352 MB compulsory traffic -> ~56us kernel floor, which this sits on.
// All traffic is provably compulsory; 128-bit is the max memory-op width on
// sm_103a. Falsified levers: coalescing shape, occupancy 22-69%, load-.cs
// (regresses), store-.cs (neutral), smem staging, SW pipelining, persistent
// grid (both serialize loads behind stores), block size, load ordering.
// sinf(theta) is load-bearing for accuracy: sqrt(1-c^2) amplifies last-bit
// error by 1/sin near theta~pi (rel_err 7e-4 vs the 1e-3 gate).

#define EPS 1e-7f
#define SMALL 1e-4f
#define ROT_ERR_W 15.0f
#define TRANS_ERR_W 100.0f

__device__ __forceinline__ void pose_compute(
    const float* __restrict__ R,   // 9 floats, row-major, this pose
    float d0, float d1, float d2,  // goal_pos - pos
    const float* __restrict__ G,   // goal rot 9
    float w0, float w1, float w2, float w3, float w4, float w5,
    float& cost, float& rot_err, float& pos_err,
    float& v0, float& v1, float& v2,
    float& o0, float& o1, float& o2)
{
    // t_ge = R^T * (g - p)
    float t0 = R[0]*d0 + R[3]*d1 + R[6]*d2;
    float t1 = R[1]*d0 + R[4]*d1 + R[7]*d2;
    float t2 = R[2]*d0 + R[5]*d1 + R[8]*d2;

    // R_ge = R^T * G : diagonal + antisymmetric off-diagonals
    float Rge00 = R[0]*G[0] + R[3]*G[3] + R[6]*G[6];
    float Rge11 = R[1]*G[1] + R[4]*G[4] + R[7]*G[7];
    float Rge22 = R[2]*G[2] + R[5]*G[5] + R[8]*G[8];
    float Rge21 = R[2]*G[1] + R[5]*G[4] + R[8]*G[7];
    float Rge12 = R[1]*G[2] + R[4]*G[5] + R[7]*G[8];
    float Rge02 = R[0]*G[2] + R[3]*G[5] + R[6]*G[8];
    float Rge20 = R[2]*G[0] + R[5]*G[3] + R[8]*G[6];
    float Rge10 = R[1]*G[0] + R[4]*G[3] + R[7]*G[6];
    float Rge01 = R[0]*G[1] + R[3]*G[4] + R[6]*G[7];

    float tr = Rge00 + Rge11 + Rge22;
    float cos_t = (tr - 1.0f) * 0.5f;
    cos_t = fminf(fmaxf(cos_t, -1.0f + EPS), 1.0f - EPS);
    float theta = acosf(cos_t);
    float sin_t = sinf(theta);   // exact reference numerics

    float wv0 = 0.5f * (Rge21 - Rge12);
    float wv1 = 0.5f * (Rge02 - Rge20);
    float wv2 = 0.5f * (Rge10 - Rge01);

    bool small = theta < SMALL;
    float scale = small ? (1.0f + theta * theta * (1.0f / 6.0f))
                        : (theta / sin_t);
    o0 = scale * wv0;
    o1 = scale * wv1;
    o2 = scale * wv2;

    float theta2 = small ? 1.0f : theta * theta;
    float A = small ? (1.0f / 12.0f)
                    : (1.0f - (theta * sin_t) / (2.0f * (1.0f - cos_t))) / theta2;

    // v = t - 0.5*(omega x t) + A*(omega*(omega.t) - |omega|^2 * t)
    float n2 = o0*o0 + o1*o1 + o2*o2;
    float ot = o0*t0 + o1*t1 + o2*t2;
    float cx0 = o1*t2 - o2*t1;
    float cx1 = o2*t0 - o0*t2;
    float cx2 = o0*t1 - o1*t0;
    v0 = t0 - 0.5f*cx0 + A*(o0*ot - n2*t0);
    v1 = t1 - 0.5f*cx1 + A*(o1*ot - n2*t1);
    v2 = t2 - 0.5f*cx2 + A*(o2*ot - n2*t2);

    float pw0 = w3*v0, pw1 = w4*v1, pw2 = w5*v2;
    float rw0 = w0*o0, rw1 = w1*o1, rw2 = w2*o2;
    pos_err = pw0*pw0 + pw1*pw1 + pw2*pw2;
    rot_err = rw0*rw0 + rw1*rw1 + rw2*rw2;
    cost = ROT_ERR_W * rot_err + TRANS_ERR_W * pos_err;
}

__global__ __launch_bounds__(256) void pose_cost_kernel_v4(
    const float* __restrict__ pos,
    const float* __restrict__ rot,
    const float* __restrict__ goal_pos,
    const float* __restrict__ goal_rot,
    const float* __restrict__ vw,
    float* __restrict__ out,
    int N4)   // N/4 groups (N divisible by 4)
{
    int g = blockIdx.x * blockDim.x + threadIdx.x;
    if (g >= N4) return;

    float G[9];
#pragma unroll
    for (int i = 0; i < 9; i++) G[i] = __ldg(&goal_rot[i]);
    float gp0 = __ldg(&goal_pos[0]);
    float gp1 = __ldg(&goal_pos[1]);
    float gp2 = __ldg(&goal_pos[2]);
    float w0 = __ldg(&vw[0]), w1 = __ldg(&vw[1]), w2 = __ldg(&vw[2]);
    float w3 = __ldg(&vw[3]), w4 = __ldg(&vw[4]), w5 = __ldg(&vw[5]);

    // ---- vectorized loads: 9 float4 rot, 3 float4 pos ----
    float Rf[36];
    const float4* Rv = (const float4*)rot + (size_t)g * 9;
#pragma unroll
    for (int i = 0; i < 9; i++) {
        float4 x = Rv[i];
        Rf[4*i+0] = x.x; Rf[4*i+1] = x.y; Rf[4*i+2] = x.z; Rf[4*i+3] = x.w;
    }
    float Pf[12];
    const float4* Pv = (const float4*)pos + (size_t)g * 3;
#pragma unroll
    for (int i = 0; i < 3; i++) {
        float4 x = Pv[i];
        Pf[4*i+0] = x.x; Pf[4*i+1] = x.y; Pf[4*i+2] = x.z; Pf[4*i+3] = x.w;
    }

    float c[4], re[4], pe[4], vv[12], om[12];
#pragma unroll
    for (int p = 0; p < 4; p++) {
        pose_compute(&Rf[9*p],
                     gp0 - Pf[3*p+0], gp1 - Pf[3*p+1], gp2 - Pf[3*p+2],
                     G, w0, w1, w2, w3, w4, w5,
                     c[p], re[p], pe[p],
                     vv[3*p+0], vv[3*p+1], vv[3*p+2],
                     om[3*p+0], om[3*p+1], om[3*p+2]);
    }

    size_t N = (size_t)N4 * 4;
    float4* out_cost = (float4*)out;
    float4* out_rot  = (float4*)(out + N);
    float4* out_pos  = (float4*)(out + 2*N);
    float4* out_v    = (float4*)(out + 3*N);
    float4* out_om   = (float4*)(out + 6*N);

    out_cost[g] = make_float4(c[0], c[1], c[2], c[3]);
    out_rot[g]  = make_float4(re[0], re[1], re[2], re[3]);
    out_pos[g]  = make_float4(pe[0], pe[1], pe[2], pe[3]);
#pragma unroll
    for (int i = 0; i < 3; i++) {
        out_v[(size_t)g*3 + i]  = make_float4(vv[4*i], vv[4*i+1], vv[4*i+2], vv[4*i+3]);
        out_om[(size_t)g*3 + i] = make_float4(om[4*i], om[4*i+1], om[4*i+2], om[4*i+3]);
    }
}

// ---- scalar fallback (N not divisible by 4) ----
__global__ __launch_bounds__(256) void pose_cost_kernel_scalar(
    const float* __restrict__ pos,
    const float* __restrict__ rot,
    const float* __restrict__ goal_pos,
    const float* __restrict__ goal_rot,
    const float* __restrict__ vw,
    float* __restrict__ out,
    int N)
{
    int idx = blockIdx.x * blockDim.x + threadIdx.x;
    if (idx >= N) return;

    float G[9];
#pragma unroll
    for (int i = 0; i < 9; i++) G[i] = __ldg(&goal_rot[i]);
    float gp0 = __ldg(&goal_pos[0]);
    float gp1 = __ldg(&goal_pos[1]);
    float gp2 = __ldg(&goal_pos[2]);
    float w0 = __ldg(&vw[0]), w1 = __ldg(&vw[1]), w2 = __ldg(&vw[2]);
    float w3 = __ldg(&vw[3]), w4 = __ldg(&vw[4]), w5 = __ldg(&vw[5]);

    float R[9];
    const float* Rp = rot + (size_t)idx * 9;
#pragma unroll
    for (int i = 0; i < 9; i++) R[i] = Rp[i];
    const float* Pp = pos + (size_t)idx * 3;

    float cost, rot_err, pos_err, v0, v1, v2, o0, o1, o2;
    pose_compute(R, gp0 - Pp[0], gp1 - Pp[1], gp2 - Pp[2],
                 G, w0, w1, w2, w3, w4, w5,
                 cost, rot_err, pos_err, v0, v1, v2, o0, o1, o2);

    out[idx] = cost;
    out[(size_t)N + idx] = rot_err;
    out[2ull*N + idx] = pos_err;
    float* ov = out + 3ull*N + (size_t)idx*3;
    ov[0] = v0; ov[1] = v1; ov[2] = v2;
    float* oo = out + 6ull*N + (size_t)idx*3;
    oo[0] = o0; oo[1] = o1; oo[2] = o2;
}

extern "C" void kernel_launch(void* const* d_in, const int* in_sizes, int n_in,
                              void* d_out, int out_size)
{
    const float* pos      = (const float*)d_in[0];
    const float* rot      = (const float*)d_in[1];
    const float* goal_pos = (const float*)d_in[2];
    const float* goal_rot = (const float*)d_in[3];
    const float* vw       = (const float*)d_in[4];

    int N = in_sizes[0] / 3;

    if ((N & 3) == 0) {
        int N4 = N >> 2;
        int threads = 256;
        int blocks = (N4 + threads - 1) / threads;
        pose_cost_kernel_v4<<<blocks, threads>>>(pos, rot, goal_pos, goal_rot, vw,
                                                 (float*)d_out, N4);
    } else {
        int threads = 256;
        int blocks = (N + threads - 1) / threads;
        pose_cost_kernel_scalar<<<blocks, threads>>>(pos, rot, goal_pos, goal_rot, vw,
                                                     (float*)d_out, N);
    }
}

// round 16
// speedup vs baseline: 1.0070x; 1.0070x over previous
#include <cuda_runtime.h>

// PoseCost: SE(3) log-map pose error, N = B*H poses.
// Outputs: [0,N) cost | [N,2N) rot_err | [2N,3N) pos_err | [3N,6N) v | [6N,9N) omega
//
// FINAL (converged, reproduced 8x: 59.42-59.52us bench, 55.5-56.8us kernel,
// DRAM 68-69.8%, rel_err 9.4e-6). 4 poses/thread, independent CTAs, all
// global traffic aligned float4, TPB=256.
//
// Session conclusion (15 rounds, 10 distinct configs): bound by ~5.5 TB/s
// sustained HBM throughput on the fixed 57/43 read/write streaming mix;
// 352 MB compulsory traffic -> ~56us kernel floor, which this sits on.
// All traffic is provably compulsory; 128-bit is the max memory-op width on
// sm_103a. Falsified levers: coalescing shape, occupancy 22-69%, load-.cs
// (regresses), store-.cs (neutral), smem staging, SW pipelining, persistent
// grid (both serialize loads behind stores), block size, load ordering.
// sinf(theta) is load-bearing for accuracy: sqrt(1-c^2) amplifies last-bit
// error by 1/sin near theta~pi (rel_err 7e-4 vs the 1e-3 gate).

#define EPS 1e-7f
#define SMALL 1e-4f
#define ROT_ERR_W 15.0f
#define TRANS_ERR_W 100.0f

__device__ __forceinline__ void pose_compute(
    const float* __restrict__ R,   // 9 floats, row-major, this pose
    float d0, float d1, float d2,  // goal_pos - pos
    const float* __restrict__ G,   // goal rot 9
    float w0, float w1, float w2, float w3, float w4, float w5,
    float& cost, float& rot_err, float& pos_err,
    float& v0, float& v1, float& v2,
    float& o0, float& o1, float& o2)
{
    // t_ge = R^T * (g - p)
    float t0 = R[0]*d0 + R[3]*d1 + R[6]*d2;
    float t1 = R[1]*d0 + R[4]*d1 + R[7]*d2;
    float t2 = R[2]*d0 + R[5]*d1 + R[8]*d2;

    // R_ge = R^T * G : diagonal + antisymmetric off-diagonals
    float Rge00 = R[0]*G[0] + R[3]*G[3] + R[6]*G[6];
    float Rge11 = R[1]*G[1] + R[4]*G[4] + R[7]*G[7];
    float Rge22 = R[2]*G[2] + R[5]*G[5] + R[8]*G[8];
    float Rge21 = R[2]*G[1] + R[5]*G[4] + R[8]*G[7];
    float Rge12 = R[1]*G[2] + R[4]*G[5] + R[7]*G[8];
    float Rge02 = R[0]*G[2] + R[3]*G[5] + R[6]*G[8];
    float Rge20 = R[2]*G[0] + R[5]*G[3] + R[8]*G[6];
    float Rge10 = R[1]*G[0] + R[4]*G[3] + R[7]*G[6];
    float Rge01 = R[0]*G[1] + R[3]*G[4] + R[6]*G[7];

    float tr = Rge00 + Rge11 + Rge22;
    float cos_t = (tr - 1.0f) * 0.5f;
    cos_t = fminf(fmaxf(cos_t, -1.0f + EPS), 1.0f - EPS);
    float theta = acosf(cos_t);
    float sin_t = sinf(theta);   // exact reference numerics

    float wv0 = 0.5f * (Rge21 - Rge12);
    float wv1 = 0.5f * (Rge02 - Rge20);
    float wv2 = 0.5f * (Rge10 - Rge01);

    bool small = theta < SMALL;
    float scale = small ? (1.0f + theta * theta * (1.0f / 6.0f))
                        : (theta / sin_t);
    o0 = scale * wv0;
    o1 = scale * wv1;
    o2 = scale * wv2;

    float theta2 = small ? 1.0f : theta * theta;
    float A = small ? (1.0f / 12.0f)
                    : (1.0f - (theta * sin_t) / (2.0f * (1.0f - cos_t))) / theta2;

    // v = t - 0.5*(omega x t) + A*(omega*(omega.t) - |omega|^2 * t)
    float n2 = o0*o0 + o1*o1 + o2*o2;
    float ot = o0*t0 + o1*t1 + o2*t2;
    float cx0 = o1*t2 - o2*t1;
    float cx1 = o2*t0 - o0*t2;
    float cx2 = o0*t1 - o1*t0;
    v0 = t0 - 0.5f*cx0 + A*(o0*ot - n2*t0);
    v1 = t1 - 0.5f*cx1 + A*(o1*ot - n2*t1);
    v2 = t2 - 0.5f*cx2 + A*(o2*ot - n2*t2);

    float pw0 = w3*v0, pw1 = w4*v1, pw2 = w5*v2;
    float rw0 = w0*o0, rw1 = w1*o1, rw2 = w2*o2;
    pos_err = pw0*pw0 + pw1*pw1 + pw2*pw2;
    rot_err = rw0*rw0 + rw1*rw1 + rw2*rw2;
    cost = ROT_ERR_W * rot_err + TRANS_ERR_W * pos_err;
}

__global__ __launch_bounds__(256) void pose_cost_kernel_v4(
    const float* __restrict__ pos,
    const float* __restrict__ rot,
    const float* __restrict__ goal_pos,
    const float* __restrict__ goal_rot,
    const float* __restrict__ vw,
    float* __restrict__ out,
    int N4)   // N/4 groups (N divisible by 4)
{
    int g = blockIdx.x * blockDim.x + threadIdx.x;
    if (g >= N4) return;

    float G[9];
#pragma unroll
    for (int i = 0; i < 9; i++) G[i] = __ldg(&goal_rot[i]);
    float gp0 = __ldg(&goal_pos[0]);
    float gp1 = __ldg(&goal_pos[1]);
    float gp2 = __ldg(&goal_pos[2]);
    float w0 = __ldg(&vw[0]), w1 = __ldg(&vw[1]), w2 = __ldg(&vw[2]);
    float w3 = __ldg(&vw[3]), w4 = __ldg(&vw[4]), w5 = __ldg(&vw[5]);

    // ---- vectorized loads: 9 float4 rot, 3 float4 pos ----
    float Rf[36];
    const float4* Rv = (const float4*)rot + (size_t)g * 9;
#pragma unroll
    for (int i = 0; i < 9; i++) {
        float4 x = Rv[i];
        Rf[4*i+0] = x.x; Rf[4*i+1] = x.y; Rf[4*i+2] = x.z; Rf[4*i+3] = x.w;
    }
    float Pf[12];
    const float4* Pv = (const float4*)pos + (size_t)g * 3;
#pragma unroll
    for (int i = 0; i < 3; i++) {
        float4 x = Pv[i];
        Pf[4*i+0] = x.x; Pf[4*i+1] = x.y; Pf[4*i+2] = x.z; Pf[4*i+3] = x.w;
    }

    float c[4], re[4], pe[4], vv[12], om[12];
#pragma unroll
    for (int p = 0; p < 4; p++) {
        pose_compute(&Rf[9*p],
                     gp0 - Pf[3*p+0], gp1 - Pf[3*p+1], gp2 - Pf[3*p+2],
                     G, w0, w1, w2, w3, w4, w5,
                     c[p], re[p], pe[p],
                     vv[3*p+0], vv[3*p+1], vv[3*p+2],
                     om[3*p+0], om[3*p+1], om[3*p+2]);
    }

    size_t N = (size_t)N4 * 4;
    float4* out_cost = (float4*)out;
    float4* out_rot  = (float4*)(out + N);
    float4* out_pos  = (float4*)(out + 2*N);
    float4* out_v    = (float4*)(out + 3*N);
    float4* out_om   = (float4*)(out + 6*N);

    out_cost[g] = make_float4(c[0], c[1], c[2], c[3]);
    out_rot[g]  = make_float4(re[0], re[1], re[2], re[3]);
    out_pos[g]  = make_float4(pe[0], pe[1], pe[2], pe[3]);
#pragma unroll
    for (int i = 0; i < 3; i++) {
        out_v[(size_t)g*3 + i]  = make_float4(vv[4*i], vv[4*i+1], vv[4*i+2], vv[4*i+3]);
        out_om[(size_t)g*3 + i] = make_float4(om[4*i], om[4*i+1], om[4*i+2], om[4*i+3]);
    }
}

// ---- scalar fallback (N not divisible by 4) ----
__global__ __launch_bounds__(256) void pose_cost_kernel_scalar(
    const float* __restrict__ pos,
    const float* __restrict__ rot,
    const float* __restrict__ goal_pos,
    const float* __restrict__ goal_rot,
    const float* __restrict__ vw,
    float* __restrict__ out,
    int N)
{
    int idx = blockIdx.x * blockDim.x + threadIdx.x;
    if (idx >= N) return;

    float G[9];
#pragma unroll
    for (int i = 0; i < 9; i++) G[i] = __ldg(&goal_rot[i]);
    float gp0 = __ldg(&goal_pos[0]);
    float gp1 = __ldg(&goal_pos[1]);
    float gp2 = __ldg(&goal_pos[2]);
    float w0 = __ldg(&vw[0]), w1 = __ldg(&vw[1]), w2 = __ldg(&vw[2]);
    float w3 = __ldg(&vw[3]), w4 = __ldg(&vw[4]), w5 = __ldg(&vw[5]);

    float R[9];
    const float* Rp = rot + (size_t)idx * 9;
#pragma unroll
    for (int i = 0; i < 9; i++) R[i] = Rp[i];
    const float* Pp = pos + (size_t)idx * 3;

    float cost, rot_err, pos_err, v0, v1, v2, o0, o1, o2;
    pose_compute(R, gp0 - Pp[0], gp1 - Pp[1], gp2 - Pp[2],
                 G, w0, w1, w2, w3, w4, w5,
                 cost, rot_err, pos_err, v0, v1, v2, o0, o1, o2);

    out[idx] = cost;
    out[(size_t)N + idx] = rot_err;
    out[2ull*N + idx] = pos_err;
    float* ov = out + 3ull*N + (size_t)idx*3;
    ov[0] = v0; ov[1] = v1; ov[2] = v2;
    float* oo = out + 6ull*N + (size_t)idx*3;
    oo[0] = o0; oo[1] = o1; oo[2] = o2;
}

extern "C" void kernel_launch(void* const* d_in, const int* in_sizes, int n_in,
                              void* d_out, int out_size)
{
    const float* pos      = (const float*)d_in[0];
    const float* rot      = (const float*)d_in[1];
    const float* goal_pos = (const float*)d_in[2];
    const float* goal_rot = (const float*)d_in[3];
    const float* vw       = (const float*)d_in[4];

    int N = in_sizes[0] / 3;

    if ((N & 3) == 0) {
        int N4 = N >> 2;
        int threads = 256;
        int blocks = (N4 + threads - 1) / threads;
        pose_cost_kernel_v4<<<blocks, threads>>>(pos, rot, goal_pos, goal_rot, vw,
                                                 (float*)d_out, N4);
    } else {
        int threads = 256;
        int blocks = (N + threads - 1) / threads;
        pose_cost_kernel_scalar<<<blocks, threads>>>(pos, rot, goal_pos, goal_rot, vw,
                                                     (float*)d_out, N);
    }
}